// round 12
// baseline (speedup 1.0000x reference)
#include <cuda_runtime.h>
#include <cstdint>

// DirectConv2d full cross-correlation (pad=2) via Winograd F(2x2,3x3), int8 IMMA.
//   inp [32,128,56,60] f32 (0..3), wgt [256,128,3,3] f32 (0..2), out [32,256,58,62] f32
//
// Scale-free transforms (halves moved into the fp32 output combine):
//   U = Ghat g Ghat^T, Ghat = [[1,0,0],[1,1,1],[1,-1,1],[0,0,1]]      (|U|<=18, s8)
//   V = B^T d B,  B^T = [[1,0,-1,0],[0,1,1,0],[0,-1,1,0],[0,1,0,-1]]  (|V|<=12, s8)
//   out(y,x) = sum_ij a[y][i]*a[x][j]*M_ij, a = [[1,.5,.5,0],[0,.5,-.5,-1]]
// M = U*V GEMM over 128 ci, s32 accum — all exact; rel_err 0.
//
// R12 change vs R11 (passed, 205.8us): software-pipelined tap loop — B gather
// prefetched into registers and combined AFTER compute, one barrier per tap.

#define OH 58
#define OW 62
#define PX 66

__device__ __align__(16) signed char g_p8[(size_t)32 * 60 * PX * 128];  // 16.2 MB
__device__ __align__(16) signed char g_U[16 * 256 * 128];               // 512 KB

// ---------------- pre-pass: U transform ----------------
__global__ __launch_bounds__(256)
void prep_U(const float* __restrict__ wgt)
{
    int idx = blockIdx.x * 256 + threadIdx.x;     // 524288
    int ci = idx & 127;
    int co = (idx >> 7) & 255;
    int t  = idx >> 15;
    int i = t >> 2, j = t & 3;
    const float* g = wgt + (size_t)(co * 128 + ci) * 9;
    float hv[3];
#pragma unroll
    for (int kw = 0; kw < 3; kw++) {
        float g0 = g[kw], g1 = g[3 + kw], g2 = g[6 + kw];
        hv[kw] = (i == 0) ? g0 : (i == 1) ? g0 + g1 + g2
               : (i == 2) ? g0 - g1 + g2 : g2;
    }
    float u = (j == 0) ? hv[0] : (j == 1) ? hv[0] + hv[1] + hv[2]
            : (j == 2) ? hv[0] - hv[1] + hv[2] : hv[2];
    g_U[idx] = (signed char)__float2int_rn(u);
}

// ---------------- pre-pass: NCHW f32 -> padded NHWC s8 ----------------
__global__ __launch_bounds__(256)
void prep_nhwc8(const float* __restrict__ inp)
{
    __shared__ signed char sh[PX][144];
    const int y   = blockIdx.x;
    const int img = blockIdx.y;
    const int tid = threadIdx.x;
    const int ih  = y - 2;
    const bool rowOK = (unsigned)ih < 56u;
    for (int it = 0; it < 33; it++) {
        int idx = it * 256 + tid;
        int x  = idx % PX;
        int ci = idx / PX;
        int iw = x - 2;
        float v = 0.0f;
        if (rowOK && (unsigned)iw < 60u)
            v = inp[((size_t)(img * 128 + ci) * 56 + ih) * 60 + iw];
        sh[x][ci] = (signed char)__float2int_rn(v);
    }
    __syncthreads();
    signed char* const ob = g_p8 + ((size_t)(img * 60 + y) * PX) * 128;
    for (int it = 0; it < 3; it++) {
        int idx = it * 256 + tid;
        if (idx >= PX * 8) break;
        int x = idx >> 3, c16 = idx & 7;
        *(uint4*)(ob + x * 128 + c16 * 16) = *(const uint4*)(&sh[x][c16 * 16]);
    }
}

// ---------------- PTX helpers ----------------
#define CP16(dst, src) \
    asm volatile("cp.async.cg.shared.global [%0], [%1], 16;" :: "r"(dst), "l"(src))
#define CP_COMMIT() asm volatile("cp.async.commit_group;" ::: "memory")
#define CP_WAIT0()  asm volatile("cp.async.wait_group 0;" ::: "memory")

#define LDSM_X4(R, addr)                                                        \
    asm volatile("ldmatrix.sync.aligned.m8n8.x4.shared.b16 {%0,%1,%2,%3}, [%4];"\
                 : "=r"((R)[0]), "=r"((R)[1]), "=r"((R)[2]), "=r"((R)[3])       \
                 : "r"(addr))
#define MMA_S8(C, A, B0, B1)                                                    \
    asm volatile("mma.sync.aligned.m16n8k32.row.col.s32.s8.s8.s32 "             \
                 "{%0,%1,%2,%3},{%4,%5,%6,%7},{%8,%9},{%0,%1,%2,%3};"           \
                 : "+r"((C)[0]), "+r"((C)[1]), "+r"((C)[2]), "+r"((C)[3])       \
                 : "r"((A)[0]), "r"((A)[1]), "r"((A)[2]), "r"((A)[3]),          \
                   "r"(B0), "r"(B1))

__device__ __forceinline__ uint32_t smem_u32(const void* p) {
    uint32_t a;
    asm("{ .reg .u64 t; cvta.to.shared.u64 t, %1; cvt.u32.u64 %0, t; }" : "=r"(a) : "l"(p));
    return a;
}
__device__ __forceinline__ uint4 v4op(uint4 a, uint4 b, bool add) {
    uint4 r;
    if (add) { r.x = __vadd4(a.x, b.x); r.y = __vadd4(a.y, b.y);
               r.z = __vadd4(a.z, b.z); r.w = __vadd4(a.w, b.w); }
    else     { r.x = __vsub4(a.x, b.x); r.y = __vsub4(a.y, b.y);
               r.z = __vsub4(a.z, b.z); r.w = __vsub4(a.w, b.w); }
    return r;
}

#define A_STAGE 18432
#define B_STAGE 4608
#define STAGE   (A_STAGE + B_STAGE)

// ---------------- main fused Winograd kernel ----------------
__global__ __launch_bounds__(256, 2)
void wino_kernel(float* __restrict__ out)
{
    __shared__ __align__(16) signed char smem[2 * STAGE];   // 46080 B
    const uint32_t s0 = smem_u32(smem);

    const int tid  = threadIdx.x;
    const int lane = tid & 31;
    const int wid  = tid >> 5;
    const int warp_m = wid >> 1;
    const int warp_n = wid & 1;
    const int coB = blockIdx.y;
    const int img = blockIdx.x / 29;
    const int ty  = blockIdx.x % 29;

    const int btx = tid >> 3, bcg = tid & 7;
    const signed char* const pb = g_p8 +
        (((size_t)img * 60 + 2 * ty) * PX + 2 * btx) * 128 + bcg * 16;

    const uint32_t aOff = (uint32_t)((warp_m * 32 + (lane & 15)) * 144 + (lane >> 4) * 16);
    const uint32_t bOff = (uint32_t)(A_STAGE +
        (warp_n * 16 + (lane & 7) + ((lane >> 4) << 3)) * 144 + ((lane >> 3) & 1) * 16);

    float OUT[2][2][4][4];
#pragma unroll
    for (int a = 0; a < 2; a++)
#pragma unroll
        for (int b = 0; b < 2; b++)
#pragma unroll
            for (int c = 0; c < 4; c++)
#pragma unroll
                for (int d = 0; d < 4; d++) OUT[a][b][c][d] = 0.0f;

    uint4 rb0, rb1, rb2, rb3;      // B prefetch quads (raw, uncombined)

    auto fillA = [&](int t, int s) {
        const signed char* src = g_U + ((size_t)t * 256 + coB * 128) * 128;
        const uint32_t dst = s0 + s * STAGE;
#pragma unroll
        for (int q = 0; q < 4; q++) {
            int idx = q * 256 + tid;
            int row = idx >> 3, seg = idx & 7;
            CP16(dst + row * 144 + seg * 16, src + row * 128 + seg * 16);
        }
    };

    auto ldgB = [&](int t) {       // issue 4 LDG.128, no combines (no stall)
        const int i = t >> 2, j = t & 3;
        const int ya = (i == 0) ? 0 : (i == 2) ? 2 : 1;
        const int yb = (i == 3) ? 3 : (i == 2) ? 1 : 2;
        const int xa = (j == 0) ? 0 : (j == 2) ? 2 : 1;
        const int xb = (j == 3) ? 3 : (j == 2) ? 1 : 2;
        rb0 = *(const uint4*)(pb + (ya * PX + xa) * 128);
        rb1 = *(const uint4*)(pb + (yb * PX + xa) * 128);
        rb2 = *(const uint4*)(pb + (ya * PX + xb) * 128);
        rb3 = *(const uint4*)(pb + (yb * PX + xb) * 128);
    };

    auto stsB = [&](int t, int s) {   // combine (data arrived during compute) + STS
        const int i = t >> 2, j = t & 3;
        uint4 ea = v4op(rb0, rb1, i == 1);
        uint4 eb = v4op(rb2, rb3, i == 1);
        uint4 v  = v4op(ea, eb, j == 1);
        *(uint4*)(smem + s * STAGE + A_STAGE + btx * 144 + bcg * 16) = v;
    };

    // ---------------- prologue ----------------
    fillA(0, 0); CP_COMMIT();
    ldgB(0); stsB(0, 0);
    CP_WAIT0();
    __syncthreads();

    // ---------------- tap loop: 1 barrier/tap, latencies hidden ----------------
#pragma unroll 1
    for (int t = 0; t < 16; t++) {
        const int s = t & 1;
        if (t < 15) {
            fillA(t + 1, s ^ 1); CP_COMMIT();
            ldgB(t + 1);
        }

        int Macc[2][2][4];
#pragma unroll
        for (int a = 0; a < 2; a++)
#pragma unroll
            for (int b = 0; b < 2; b++)
#pragma unroll
                for (int c = 0; c < 4; c++) Macc[a][b][c] = 0;

        const uint32_t sb = s0 + s * STAGE;
#pragma unroll
        for (int ks = 0; ks < 4; ks++) {
            unsigned af[2][4], bf[4];
#pragma unroll
            for (int mi = 0; mi < 2; mi++)
                LDSM_X4(af[mi], sb + aOff + mi * (16 * 144) + ks * 32);
            LDSM_X4(bf, sb + bOff + ks * 32);
#pragma unroll
            for (int mi = 0; mi < 2; mi++)
#pragma unroll
                for (int nj = 0; nj < 2; nj++)
                    MMA_S8(Macc[mi][nj], af[mi], bf[nj * 2], bf[nj * 2 + 1]);
        }

        // fused output transform (dyadic coeffs, fp32 exact)
        const int i = t >> 2, j = t & 3;
        const float cy0 = (i == 0) ? 1.f : (i == 3) ? 0.f : 0.5f;
        const float cy1 = (i == 0) ? 0.f : (i == 1) ? 0.5f : (i == 2) ? -0.5f : -1.f;
        const float cx0 = (j == 0) ? 1.f : (j == 3) ? 0.f : 0.5f;
        const float cx1 = (j == 0) ? 0.f : (j == 1) ? 0.5f : (j == 2) ? -0.5f : -1.f;
        const float c00 = cy0 * cx0, c01 = cy0 * cx1, c10 = cy1 * cx0, c11 = cy1 * cx1;
#pragma unroll
        for (int mi = 0; mi < 2; mi++)
#pragma unroll
            for (int nj = 0; nj < 2; nj++)
#pragma unroll
                for (int r = 0; r < 4; r++) {
                    const float f = (float)Macc[mi][nj][r];
                    if (c00 != 0.f) OUT[mi][nj][r][0] += c00 * f;
                    if (c01 != 0.f) OUT[mi][nj][r][1] += c01 * f;
                    if (c10 != 0.f) OUT[mi][nj][r][2] += c10 * f;
                    if (c11 != 0.f) OUT[mi][nj][r][3] += c11 * f;
                }

        if (t < 15) stsB(t + 1, s ^ 1);
        CP_WAIT0();          // A(t+1) landed (issued a full compute phase ago)
        __syncthreads();     // stage s reads + stage s^1 writes complete
    }

    // ---------------- epilogue: 2x2 output pixels per (co, tile) ----------------
    const int g  = lane >> 2;
    const int tg = lane & 3;
#pragma unroll
    for (int mi = 0; mi < 2; mi++)
#pragma unroll
        for (int nj = 0; nj < 2; nj++)
#pragma unroll
            for (int r = 0; r < 4; r++) {
                const int tx = warp_n * 16 + nj * 8 + tg * 2 + (r & 1);
                if (tx >= 31) continue;
                const int co = coB * 128 + warp_m * 32 + mi * 16 + g + ((r >= 2) ? 8 : 0);
                float* ob = out + (((size_t)(img * 256 + co) * OH + 2 * ty) * OW + 2 * tx);
                *(float2*)ob        = make_float2(OUT[mi][nj][r][0], OUT[mi][nj][r][1]);
                *(float2*)(ob + OW) = make_float2(OUT[mi][nj][r][2], OUT[mi][nj][r][3]);
            }
}

extern "C" void kernel_launch(void* const* d_in, const int* in_sizes, int n_in,
                              void* d_out, int out_size)
{
    const float* inp = (const float*)d_in[0];
    const float* wgt = (const float*)d_in[1];
    float* out = (float*)d_out;

    prep_U<<<2048, 256>>>(wgt);
    prep_nhwc8<<<dim3(60, 32), 256>>>(inp);
    wino_kernel<<<dim3(32 * 29, 2), 256>>>(out);
}

// round 13
// speedup vs baseline: 1.0792x; 1.0792x over previous
#include <cuda_runtime.h>
#include <cstdint>

// DirectConv2d full cross-correlation (pad=2) via Winograd F(2x2,3x3), int8 IMMA.
//   inp [32,128,56,60] f32 (0..3), wgt [256,128,3,3] f32 (0..2), out [32,256,58,62] f32
//
// U = Ghat g Ghat^T (|U|<=18, s8), V = B^T d B (|V|<=12, s8),
// out = sum_ij a[y][i]a[x][j] M_ij, M = U*V over 128 ci (s32, exact). rel_err 0.
//
// R13 vs R11 (205.8us): A operands stored in GLOBAL in mma-fragment order and
// loaded straight to registers (1 LDG.128 per warp per (mi,ks)) — the whole A
// smem pipeline (cp.async/commit/wait/ldmatrix) is gone. B uses a 3-stage smem
// ring -> ONE __syncthreads per tap with no extra live registers.

#define OH 58
#define OW 62
#define PX 66

__device__ __align__(16) signed char g_p8[(size_t)32 * 60 * PX * 128];   // 16.2 MB
// fragment-ordered U: block(t,coB,wm,mi,ks) of 512B, lane*16 inside   (512 KB)
__device__ __align__(16) signed char g_Ufrag[16 * 2 * 4 * 2 * 4 * 512];

// ---------------- combined pre-pass (one launch) ----------------
__global__ __launch_bounds__(256)
void prep_all(const float* __restrict__ inp, const float* __restrict__ wgt)
{
    if (blockIdx.x >= 1920) {
        // U transform -> fragment layout
        int idx = (blockIdx.x - 1920) * 256 + threadIdx.x;    // 524288
        int ci = idx & 127;
        int co = (idx >> 7) & 255;
        int t  = idx >> 15;
        int i = t >> 2, j = t & 3;
        const float* g = wgt + (size_t)(co * 128 + ci) * 9;
        float hv[3];
#pragma unroll
        for (int kw = 0; kw < 3; kw++) {
            float g0 = g[kw], g1 = g[3 + kw], g2 = g[6 + kw];
            hv[kw] = (i == 0) ? g0 : (i == 1) ? g0 + g1 + g2
                   : (i == 2) ? g0 - g1 + g2 : g2;
        }
        float u = (j == 0) ? hv[0] : (j == 1) ? hv[0] + hv[1] + hv[2]
                : (j == 2) ? hv[0] - hv[1] + hv[2] : hv[2];
        // fragment address (inverse of the ldsm.x4 mapping validated in R8/R11)
        int coB = co >> 7, wm = (co >> 5) & 3;
        int r5 = co & 31,  mi = r5 >> 4, rr = r5 & 15;
        int qb = rr >> 3,  lh = rr & 7;
        int ks = ci >> 5,  cr = ci & 31;
        int qh = cr >> 4,  cl = cr & 15;
        int l  = lh * 4 + (cl >> 2);
        int q  = qh * 2 + qb;
        g_Ufrag[(size_t)(((((t * 2 + coB) * 4 + wm) * 2 + mi) * 4 + ks)) * 512
                + l * 16 + q * 4 + (cl & 3)] = (signed char)__float2int_rn(u);
        return;
    }
    // NCHW f32 -> padded NHWC s8 (proven R8/R11 shape)
    __shared__ signed char sh[PX][144];
    const int y   = blockIdx.x % 60;
    const int img = blockIdx.x / 60;
    const int tid = threadIdx.x;
    const int ih  = y - 2;
    const bool rowOK = (unsigned)ih < 56u;
    for (int it = 0; it < 33; it++) {
        int idx = it * 256 + tid;
        int x  = idx % PX;
        int ci = idx / PX;
        int iw = x - 2;
        float v = 0.0f;
        if (rowOK && (unsigned)iw < 60u)
            v = inp[((size_t)(img * 128 + ci) * 56 + ih) * 60 + iw];
        sh[x][ci] = (signed char)__float2int_rn(v);
    }
    __syncthreads();
    signed char* const ob = g_p8 + ((size_t)(img * 60 + y) * PX) * 128;
    for (int it = 0; it < 3; it++) {
        int idx = it * 256 + tid;
        if (idx >= PX * 8) break;
        int x = idx >> 3, c16 = idx & 7;
        *(uint4*)(ob + x * 128 + c16 * 16) = *(const uint4*)(&sh[x][c16 * 16]);
    }
}

// ---------------- PTX helpers ----------------
#define LDSM_X4(R, addr)                                                        \
    asm volatile("ldmatrix.sync.aligned.m8n8.x4.shared.b16 {%0,%1,%2,%3}, [%4];"\
                 : "=r"((R)[0]), "=r"((R)[1]), "=r"((R)[2]), "=r"((R)[3])       \
                 : "r"(addr))
#define MMA_S8(C, A0, A1, A2, A3, B0, B1)                                       \
    asm volatile("mma.sync.aligned.m16n8k32.row.col.s32.s8.s8.s32 "             \
                 "{%0,%1,%2,%3},{%4,%5,%6,%7},{%8,%9},{%0,%1,%2,%3};"           \
                 : "+r"((C)[0]), "+r"((C)[1]), "+r"((C)[2]), "+r"((C)[3])       \
                 : "r"(A0), "r"(A1), "r"(A2), "r"(A3), "r"(B0), "r"(B1))

__device__ __forceinline__ uint32_t smem_u32(const void* p) {
    uint32_t a;
    asm("{ .reg .u64 t; cvta.to.shared.u64 t, %1; cvt.u32.u64 %0, t; }" : "=r"(a) : "l"(p));
    return a;
}
__device__ __forceinline__ uint4 v4op(uint4 a, uint4 b, bool add) {
    uint4 r;
    if (add) { r.x = __vadd4(a.x, b.x); r.y = __vadd4(a.y, b.y);
               r.z = __vadd4(a.z, b.z); r.w = __vadd4(a.w, b.w); }
    else     { r.x = __vsub4(a.x, b.x); r.y = __vsub4(a.y, b.y);
               r.z = __vsub4(a.z, b.z); r.w = __vsub4(a.w, b.w); }
    return r;
}

#define B_STAGE 4608              // 32 rows x 144B

// ---------------- main kernel ----------------
__global__ __launch_bounds__(256, 2)
void wino_kernel(float* __restrict__ out)
{
    __shared__ __align__(16) signed char smem[3 * B_STAGE];   // 13824 B
    const uint32_t s0 = smem_u32(smem);

    const int tid  = threadIdx.x;
    const int lane = tid & 31;
    const int wid  = tid >> 5;
    const int warp_m = wid >> 1;
    const int warp_n = wid & 1;
    const int coB = blockIdx.y;
    const int img = blockIdx.x / 29;
    const int ty  = blockIdx.x % 29;

    const int btx = tid >> 3, bcg = tid & 7;
    const signed char* const pb = g_p8 +
        (((size_t)img * 60 + 2 * ty) * PX + 2 * btx) * 128 + bcg * 16;

    // A fragment base for this warp (lane-resolved); per tap add t*32768
    const signed char* const aw = g_Ufrag + (size_t)(coB * 32 + warp_m * 8) * 512 + lane * 16;

    const uint32_t bOff = (uint32_t)(
        (warp_n * 16 + (lane & 7) + ((lane >> 4) << 3)) * 144 + ((lane >> 3) & 1) * 16);

    float OUT[2][2][4][4];
#pragma unroll
    for (int a = 0; a < 2; a++)
#pragma unroll
        for (int b = 0; b < 2; b++)
#pragma unroll
            for (int c = 0; c < 4; c++)
#pragma unroll
                for (int d = 0; d < 4; d++) OUT[a][b][c][d] = 0.0f;

    auto fillB = [&](int t, int st) {
        const int i = t >> 2, j = t & 3;
        const int ya = (i == 0) ? 0 : (i == 2) ? 2 : 1;
        const int yb = (i == 3) ? 3 : (i == 2) ? 1 : 2;
        const int xa = (j == 0) ? 0 : (j == 2) ? 2 : 1;
        const int xb = (j == 3) ? 3 : (j == 2) ? 1 : 2;
        uint4 daa = *(const uint4*)(pb + (ya * PX + xa) * 128);
        uint4 dba = *(const uint4*)(pb + (yb * PX + xa) * 128);
        uint4 dab = *(const uint4*)(pb + (ya * PX + xb) * 128);
        uint4 dbb = *(const uint4*)(pb + (yb * PX + xb) * 128);
        uint4 ea = v4op(daa, dba, i == 1);
        uint4 eb = v4op(dab, dbb, i == 1);
        uint4 v  = v4op(ea, eb, j == 1);
        *(uint4*)(smem + st * B_STAGE + btx * 144 + bcg * 16) = v;
    };

    // ---------------- tap loop: 3-stage B ring, ONE barrier per tap ----------------
    // compute(t) reads stage t%3; fillB(t+1) writes (t+1)%3; the conflicting
    // reader of (t+1)%3 is compute(t-2), separated by two earlier syncs. Safe.
    fillB(0, 0);
#pragma unroll 1
    for (int t = 0; t < 16; t++) {
        if (t < 15) fillB(t + 1, (t + 1) % 3);
        __syncthreads();

        int Macc[2][2][4];
#pragma unroll
        for (int a = 0; a < 2; a++)
#pragma unroll
            for (int b = 0; b < 2; b++)
#pragma unroll
                for (int c = 0; c < 4; c++) Macc[a][b][c] = 0;

        const uint32_t sb = s0 + (t % 3) * B_STAGE + bOff;
        const signed char* const at = aw + (size_t)t * 32768;
#pragma unroll
        for (int ks = 0; ks < 4; ks++) {
            uint4 a0 = *(const uint4*)(at + ks * 512);          // mi=0
            uint4 a1 = *(const uint4*)(at + (4 + ks) * 512);    // mi=1
            unsigned bf[4];
            LDSM_X4(bf, sb + ks * 32);
#pragma unroll
            for (int nj = 0; nj < 2; nj++) {
                MMA_S8(Macc[0][nj], a0.x, a0.y, a0.z, a0.w, bf[nj * 2], bf[nj * 2 + 1]);
                MMA_S8(Macc[1][nj], a1.x, a1.y, a1.z, a1.w, bf[nj * 2], bf[nj * 2 + 1]);
            }
        }

        // fused output transform (dyadic coeffs, fp32 exact)
        const int i = t >> 2, j = t & 3;
        const float cy0 = (i == 0) ? 1.f : (i == 3) ? 0.f : 0.5f;
        const float cy1 = (i == 0) ? 0.f : (i == 1) ? 0.5f : (i == 2) ? -0.5f : -1.f;
        const float cx0 = (j == 0) ? 1.f : (j == 3) ? 0.f : 0.5f;
        const float cx1 = (j == 0) ? 0.f : (j == 1) ? 0.5f : (j == 2) ? -0.5f : -1.f;
        const float c00 = cy0 * cx0, c01 = cy0 * cx1, c10 = cy1 * cx0, c11 = cy1 * cx1;
#pragma unroll
        for (int mi = 0; mi < 2; mi++)
#pragma unroll
            for (int nj = 0; nj < 2; nj++)
#pragma unroll
                for (int r = 0; r < 4; r++) {
                    const float f = (float)Macc[mi][nj][r];
                    if (c00 != 0.f) OUT[mi][nj][r][0] += c00 * f;
                    if (c01 != 0.f) OUT[mi][nj][r][1] += c01 * f;
                    if (c10 != 0.f) OUT[mi][nj][r][2] += c10 * f;
                    if (c11 != 0.f) OUT[mi][nj][r][3] += c11 * f;
                }
    }

    // ---------------- epilogue (unchanged, proven) ----------------
    const int g  = lane >> 2;
    const int tg = lane & 3;
#pragma unroll
    for (int mi = 0; mi < 2; mi++)
#pragma unroll
        for (int nj = 0; nj < 2; nj++)
#pragma unroll
            for (int r = 0; r < 4; r++) {
                const int tx = warp_n * 16 + nj * 8 + tg * 2 + (r & 1);
                if (tx >= 31) continue;
                const int co = coB * 128 + warp_m * 32 + mi * 16 + g + ((r >= 2) ? 8 : 0);
                float* ob = out + (((size_t)(img * 256 + co) * OH + 2 * ty) * OW + 2 * tx);
                *(float2*)ob        = make_float2(OUT[mi][nj][r][0], OUT[mi][nj][r][1]);
                *(float2*)(ob + OW) = make_float2(OUT[mi][nj][r][2], OUT[mi][nj][r][3]);
            }
}

extern "C" void kernel_launch(void* const* d_in, const int* in_sizes, int n_in,
                              void* d_out, int out_size)
{
    const float* inp = (const float*)d_in[0];
    const float* wgt = (const float*)d_in[1];
    float* out = (float*)d_out;

    prep_all<<<1920 + 2048, 256>>>(inp, wgt);
    wino_kernel<<<dim3(32 * 29, 2), 256>>>(out);
}